// round 3
// baseline (speedup 1.0000x reference)
#include <cuda_runtime.h>
#include <cstdint>

#define P_DROP   0.1f
#define ALPHA_F  0.1f
#define NUM_HOPS 10

// Fixed problem capacities (APPNP_88175678587122: N=100000, E=3200000, IN=512, HID=64, OUT=64)
#define MAXN   100352
#define MAXE   3200000
#define MAXNI  51200000   // N*IN
#define MAXNH  6400000    // N*HID / N*OUT

// ---------------- static device scratch (no allocations allowed) ----------------
__device__ float    g_Xd[MAXNI];
__device__ float    g_H[MAXNH];
__device__ float    g_Z0[MAXNH];
__device__ float    g_Za[MAXNH];
__device__ float    g_Zb[MAXNH];
__device__ int      g_cnt[MAXN];
__device__ int      g_rowptr[MAXN + 1];
__device__ int      g_fill[MAXN];
__device__ int      g_colcsr[MAXE];
__device__ unsigned g_eid[MAXE];
__device__ float    g_w[(size_t)NUM_HOPS * MAXE];

// ---------------- threefry-2x32 (JAX-exact, 20 rounds) ----------------
__host__ __device__ __forceinline__ void tf_block(unsigned k0, unsigned k1,
                                                  unsigned x0, unsigned x1,
                                                  unsigned& o0, unsigned& o1) {
    unsigned k2 = k0 ^ k1 ^ 0x1BD11BDAu;
    x0 += k0; x1 += k1;
#define TF_R(r) { x0 += x1; x1 = (x1 << (r)) | (x1 >> (32 - (r))); x1 ^= x0; }
    TF_R(13) TF_R(15) TF_R(26) TF_R(6)
    x0 += k1; x1 += k2 + 1u;
    TF_R(17) TF_R(29) TF_R(16) TF_R(24)
    x0 += k2; x1 += k0 + 2u;
    TF_R(13) TF_R(15) TF_R(26) TF_R(6)
    x0 += k0; x1 += k1 + 3u;
    TF_R(17) TF_R(29) TF_R(16) TF_R(24)
    x0 += k1; x1 += k2 + 4u;
    TF_R(13) TF_R(15) TF_R(26) TF_R(6)
    x0 += k2; x1 += k0 + 5u;
#undef TF_R
    o0 = x0; o1 = x1;
}

// partitionable-mode random bits: element i -> block(key, hi(i)=0, lo(i)=i), b1^b2
__device__ __forceinline__ unsigned tf_bits(unsigned k0, unsigned k1, unsigned lo) {
    unsigned a, b;
    tf_block(k0, k1, 0u, lo, a, b);
    return a ^ b;
}

__device__ __forceinline__ float tf_uniform(unsigned bits) {
    return __uint_as_float(0x3f800000u | (bits >> 9)) - 1.0f;
}

// ---------------- CSR build ----------------
__global__ void zero_cnt_kernel(int n) {
    int i = blockIdx.x * blockDim.x + threadIdx.x;
    if (i < n) g_cnt[i] = 0;
}

__global__ void hist_kernel(const int* __restrict__ index, int E) {
    int e = blockIdx.x * blockDim.x + threadIdx.x;
    if (e < E) atomicAdd(&g_cnt[index[e]], 1);   // index[0..E) = row
}

__global__ void scan_kernel(int N, int E) {
    __shared__ int sm[1024];
    int t = threadIdx.x;
    int chunk = (N + 1023) >> 10;
    int beg = t * chunk; if (beg > N) beg = N;
    int end = beg + chunk; if (end > N) end = N;
    int s = 0;
    for (int i = beg; i < end; i++) s += g_cnt[i];
    sm[t] = s;
    __syncthreads();
    for (int off = 1; off < 1024; off <<= 1) {
        int v = (t >= off) ? sm[t - off] : 0;
        __syncthreads();
        sm[t] += v;
        __syncthreads();
    }
    int run = sm[t] - s;   // exclusive prefix
    for (int i = beg; i < end; i++) {
        g_rowptr[i] = run;
        g_fill[i]   = run;
        run += g_cnt[i];
    }
    if (t == 1023) g_rowptr[N] = E;
}

__global__ void scatter_kernel(const int* __restrict__ index, int E) {
    int e = blockIdx.x * blockDim.x + threadIdx.x;
    if (e < E) {
        int r = index[e];
        int c = index[E + e];
        int pos = atomicAdd(&g_fill[r], 1);
        g_colcsr[pos] = c;
        g_eid[pos]    = (unsigned)e;
    }
}

// ---------------- per-hop edge weights (edge dropout, JAX-exact mask) ----------------
struct HopKeys { unsigned a[NUM_HOPS]; unsigned b[NUM_HOPS]; };

__global__ void edgew_kernel(const float* __restrict__ value, int E, HopKeys hk,
                             float keep, float invkeep, float onemA) {
    int pos = blockIdx.x * blockDim.x + threadIdx.x;
    if (pos >= E) return;
    unsigned e = g_eid[pos];
    float w_keep = onemA * (value[e] * invkeep);   // (1-alpha) * value/keep
#pragma unroll
    for (int h = 0; h < NUM_HOPS; h++) {
        unsigned bits = tf_bits(hk.a[h], hk.b[h], e);
        float u = tf_uniform(bits);
        g_w[(size_t)h * E + pos] = (u < keep) ? w_keep : 0.0f;
    }
}

// ---------------- dropout passes ----------------
__global__ void dropx_kernel(const float* __restrict__ X, int n,
                             unsigned k0, unsigned k1, float keep, float invkeep) {
    int i = blockIdx.x * blockDim.x + threadIdx.x;
    if (i >= n) return;
    unsigned bits = tf_bits(k0, k1, (unsigned)i);
    float u = tf_uniform(bits);
    g_Xd[i] = (u < keep) ? X[i] * invkeep : 0.0f;
}

__global__ void droph_kernel(int n, unsigned k0, unsigned k1, float keep, float invkeep) {
    int i = blockIdx.x * blockDim.x + threadIdx.x;
    if (i >= n) return;
    unsigned bits = tf_bits(k0, k1, (unsigned)i);
    float u = tf_uniform(bits);
    float x = g_H[i];
    g_H[i] = (u < keep) ? x * invkeep : 0.0f;
}

// ---------------- fp32 SIMT GEMM: O = act(A @ W + b), BN = Ncols = 64 ----------------
// mode 0: A=g_Xd -> g_H, relu.  mode 1: A=g_H -> g_Z0, no relu.
#define BM 64
#define BN 64
#define BK 32
__global__ __launch_bounds__(256) void gemm_kernel(int mode,
                                                   const float* __restrict__ W,
                                                   const float* __restrict__ bias,
                                                   int Nrows, int K) {
    const float* __restrict__ A = (mode == 0) ? g_Xd : g_H;
    float* __restrict__ O       = (mode == 0) ? g_H  : g_Z0;
    __shared__ float As[BM][BK + 1];
    __shared__ float Ws[BK][BN];
    int tid = threadIdx.x;
    int tx = tid & 15, ty = tid >> 4;
    int rowBase = blockIdx.x * BM;
    float acc[4][4] = {};
    for (int k0 = 0; k0 < K; k0 += BK) {
#pragma unroll
        for (int l = 0; l < 2; l++) {
            int idx = tid + l * 256;           // 512 float4 slots: A tile 64x32
            int r = idx >> 3, c4 = idx & 7;
            int gr = rowBase + r;
            float4 v = make_float4(0.f, 0.f, 0.f, 0.f);
            if (gr < Nrows) v = *(const float4*)&A[(size_t)gr * K + k0 + c4 * 4];
            As[r][c4 * 4 + 0] = v.x; As[r][c4 * 4 + 1] = v.y;
            As[r][c4 * 4 + 2] = v.z; As[r][c4 * 4 + 3] = v.w;
        }
#pragma unroll
        for (int l = 0; l < 2; l++) {
            int idx = tid + l * 256;           // W tile 32x64 -> 512 float4
            int r = idx >> 4, c4 = idx & 15;
            float4 v = *(const float4*)&W[(size_t)(k0 + r) * BN + c4 * 4];
            *(float4*)&Ws[r][c4 * 4] = v;
        }
        __syncthreads();
#pragma unroll
        for (int k = 0; k < BK; k++) {
            float a0 = As[ty * 4 + 0][k], a1 = As[ty * 4 + 1][k];
            float a2 = As[ty * 4 + 2][k], a3 = As[ty * 4 + 3][k];
            float4 w = *(float4*)&Ws[k][tx * 4];
            acc[0][0] += a0 * w.x; acc[0][1] += a0 * w.y; acc[0][2] += a0 * w.z; acc[0][3] += a0 * w.w;
            acc[1][0] += a1 * w.x; acc[1][1] += a1 * w.y; acc[1][2] += a1 * w.z; acc[1][3] += a1 * w.w;
            acc[2][0] += a2 * w.x; acc[2][1] += a2 * w.y; acc[2][2] += a2 * w.z; acc[2][3] += a2 * w.w;
            acc[3][0] += a3 * w.x; acc[3][1] += a3 * w.y; acc[3][2] += a3 * w.z; acc[3][3] += a3 * w.w;
        }
        __syncthreads();
    }
    float4 bv = *(const float4*)&bias[tx * 4];
#pragma unroll
    for (int i = 0; i < 4; i++) {
        int gr = rowBase + ty * 4 + i;
        if (gr < Nrows) {
            float4 o;
            o.x = acc[i][0] + bv.x; o.y = acc[i][1] + bv.y;
            o.z = acc[i][2] + bv.z; o.w = acc[i][3] + bv.w;
            if (mode == 0) {
                o.x = fmaxf(o.x, 0.f); o.y = fmaxf(o.y, 0.f);
                o.z = fmaxf(o.z, 0.f); o.w = fmaxf(o.w, 0.f);
            }
            *(float4*)&O[(size_t)gr * BN + tx * 4] = o;
        }
    }
}

// ---------------- propagation hop: one warp per destination row (pull, no atomics) ----------------
__global__ __launch_bounds__(256) void hop_kernel(int hop, int lastHop,
                                                  float* __restrict__ dout,
                                                  int Nrows, int E, float alpha) {
    const float* __restrict__ Zin =
        (hop == 0) ? g_Z0 : ((hop & 1) ? g_Za : g_Zb);
    float* __restrict__ Zout =
        (hop == lastHop) ? dout : ((hop & 1) ? g_Zb : g_Za);
    const float* __restrict__ wh = &g_w[(size_t)hop * E];

    int warp = (int)((blockIdx.x * (unsigned)blockDim.x + threadIdx.x) >> 5);
    int lane = threadIdx.x & 31;
    if (warp >= Nrows) return;
    int s = g_rowptr[warp];
    int e = g_rowptr[warp + 1];
    float ax = 0.f, ay = 0.f;
    int j = s;
    // 2-way unrolled: keep two independent Z-row loads in flight
    for (; j + 2 <= e; j += 2) {
        float w0 = __ldg(&wh[j]);
        float w1 = __ldg(&wh[j + 1]);
        int  c0 = __ldg(&g_colcsr[j]);
        int  c1 = __ldg(&g_colcsr[j + 1]);
        if (w0 != 0.0f) {
            float2 z = *(const float2*)&Zin[(size_t)c0 * 64 + lane * 2];
            ax = fmaf(w0, z.x, ax);
            ay = fmaf(w0, z.y, ay);
        }
        if (w1 != 0.0f) {
            float2 z = *(const float2*)&Zin[(size_t)c1 * 64 + lane * 2];
            ax = fmaf(w1, z.x, ax);
            ay = fmaf(w1, z.y, ay);
        }
    }
    for (; j < e; j++) {
        float ww = __ldg(&wh[j]);
        if (ww != 0.0f) {
            int c = __ldg(&g_colcsr[j]);
            float2 z = *(const float2*)&Zin[(size_t)c * 64 + lane * 2];
            ax = fmaf(ww, z.x, ax);
            ay = fmaf(ww, z.y, ay);
        }
    }
    float2 z0 = *(const float2*)&g_Z0[(size_t)warp * 64 + lane * 2];
    float2 o;
    o.x = ax + alpha * z0.x;
    o.y = ay + alpha * z0.y;
    *(float2*)&Zout[(size_t)warp * 64 + lane * 2] = o;
}

// ---------------- host ----------------
extern "C" void kernel_launch(void* const* d_in, const int* in_sizes, int n_in,
                              void* d_out, int out_size) {
    const int*   index = (const int*)d_in[0];
    const float* value = (const float*)d_in[1];
    // Optional scalar "n" may appear as a size-1 input at slot 2.
    int base = (n_in >= 8 && in_sizes[2] == 1) ? 3 : 2;
    const float* X  = (const float*)d_in[base + 0];
    const float* W1 = (const float*)d_in[base + 1];
    const float* b1 = (const float*)d_in[base + 2];
    const float* W2 = (const float*)d_in[base + 3];
    const float* b2 = (const float*)d_in[base + 4];

    int E   = in_sizes[1];
    int HID = in_sizes[base + 2];
    int OUT = in_sizes[base + 4];
    int IN  = in_sizes[base + 1] / HID;
    int N   = in_sizes[base + 0] / IN;
    (void)out_size; (void)OUT;

    // ---- derive JAX keys on host (key(42), fold-like split, fold_in) ----
    unsigned rk0 = 0u, rk1 = 42u;
    unsigned kx0, kx1, kh0, kh1, ke0, ke1;
    tf_block(rk0, rk1, 0u, 0u, kx0, kx1);   // split[0]
    tf_block(rk0, rk1, 0u, 1u, kh0, kh1);   // split[1]
    tf_block(rk0, rk1, 0u, 2u, ke0, ke1);   // split[2]
    HopKeys hk;
    for (unsigned h = 0; h < NUM_HOPS; h++)
        tf_block(ke0, ke1, 0u, h, hk.a[h], hk.b[h]);   // fold_in(ke, h)

    const float keep    = 1.0f - P_DROP;          // 0.9f
    const float invkeep = 1.0f / keep;
    const float onemA   = 1.0f - ALPHA_F;

    const int T = 256;

    // ---- CSR build (per launch; deterministic structure up to edge order) ----
    zero_cnt_kernel<<<(N + T - 1) / T, T>>>(N);
    hist_kernel<<<(E + T - 1) / T, T>>>(index, E);
    scan_kernel<<<1, 1024>>>(N, E);
    scatter_kernel<<<(E + T - 1) / T, T>>>(index, E);

    // ---- per-hop edge weights ----
    edgew_kernel<<<(E + T - 1) / T, T>>>(value, E, hk, keep, invkeep, onemA);

    // ---- MLP: dropout -> GEMM(relu) -> dropout -> GEMM ----
    int SX = N * IN;
    dropx_kernel<<<(SX + T - 1) / T, T>>>(X, SX, kx0, kx1, keep, invkeep);
    gemm_kernel<<<(N + BM - 1) / BM, 256>>>(0, W1, b1, N, IN);
    int SH = N * HID;
    droph_kernel<<<(SH + T - 1) / T, T>>>(SH, kh0, kh1, keep, invkeep);
    gemm_kernel<<<(N + BM - 1) / BM, 256>>>(1, W2, b2, N, HID);

    // ---- 10 propagation hops ----
    int warps = N;
    int hopBlocks = (warps * 32 + T - 1) / T;
    for (int h = 0; h < NUM_HOPS; h++)
        hop_kernel<<<hopBlocks, T>>>(h, NUM_HOPS - 1, (float*)d_out, N, E, ALPHA_F);
}

// round 4
// speedup vs baseline: 1.1420x; 1.1420x over previous
#include <cuda_runtime.h>
#include <cstdint>

#define P_DROP   0.1f
#define ALPHA_F  0.1f
#define NUM_HOPS 10

// Fixed problem capacities (N=100000, E=3200000, IN=512, HID=64, OUT=64)
#define MAXN   100352
#define MAXE   3200000
#define MAXNH  6400000    // N*HID / N*OUT

// ---------------- static device scratch (no allocations allowed) ----------------
__device__ float              g_H[MAXNH];
__device__ float              g_Z0[MAXNH];
__device__ float              g_Za[MAXNH];
__device__ float              g_Zb[MAXNH];
__device__ int                g_cnt[MAXN];
__device__ int                g_rowptr[MAXN + 1];
__device__ int                g_fill[MAXN];
// packed per-CSR-position edge record: lo32 = col | (10-bit hop keep-mask << 22), hi32 = f32 weight
__device__ unsigned long long g_cw[MAXE];

// ---------------- threefry-2x32 (JAX-exact, 20 rounds) ----------------
__host__ __device__ __forceinline__ void tf_block(unsigned k0, unsigned k1,
                                                  unsigned x0, unsigned x1,
                                                  unsigned& o0, unsigned& o1) {
    unsigned k2 = k0 ^ k1 ^ 0x1BD11BDAu;
    x0 += k0; x1 += k1;
#define TF_R(r) { x0 += x1; x1 = (x1 << (r)) | (x1 >> (32 - (r))); x1 ^= x0; }
    TF_R(13) TF_R(15) TF_R(26) TF_R(6)
    x0 += k1; x1 += k2 + 1u;
    TF_R(17) TF_R(29) TF_R(16) TF_R(24)
    x0 += k2; x1 += k0 + 2u;
    TF_R(13) TF_R(15) TF_R(26) TF_R(6)
    x0 += k0; x1 += k1 + 3u;
    TF_R(17) TF_R(29) TF_R(16) TF_R(24)
    x0 += k1; x1 += k2 + 4u;
    TF_R(13) TF_R(15) TF_R(26) TF_R(6)
    x0 += k2; x1 += k0 + 5u;
#undef TF_R
    o0 = x0; o1 = x1;
}

// partitionable-mode random bits: element i -> block(key, hi=0, lo=i), b1^b2
__device__ __forceinline__ unsigned tf_bits(unsigned k0, unsigned k1, unsigned lo) {
    unsigned a, b;
    tf_block(k0, k1, 0u, lo, a, b);
    return a ^ b;
}

__device__ __forceinline__ float tf_uniform(unsigned bits) {
    return __uint_as_float(0x3f800000u | (bits >> 9)) - 1.0f;
}

struct HopKeys { unsigned a[NUM_HOPS]; unsigned b[NUM_HOPS]; };

// ---------------- CSR build ----------------
__global__ void zero_cnt_kernel(int n) {
    int i = blockIdx.x * blockDim.x + threadIdx.x;
    if (i < n) g_cnt[i] = 0;
}

__global__ void hist_kernel(const int* __restrict__ index, int E) {
    int e = blockIdx.x * blockDim.x + threadIdx.x;
    if (e < E) atomicAdd(&g_cnt[index[e]], 1);   // index[0..E) = row
}

__global__ void scan_kernel(int N, int E) {
    __shared__ int sm[1024];
    int t = threadIdx.x;
    int chunk = (N + 1023) >> 10;
    int beg = t * chunk; if (beg > N) beg = N;
    int end = beg + chunk; if (end > N) end = N;
    int s = 0;
    for (int i = beg; i < end; i++) s += g_cnt[i];
    sm[t] = s;
    __syncthreads();
    for (int off = 1; off < 1024; off <<= 1) {
        int v = (t >= off) ? sm[t - off] : 0;
        __syncthreads();
        sm[t] += v;
        __syncthreads();
    }
    int run = sm[t] - s;   // exclusive prefix
    for (int i = beg; i < end; i++) {
        g_rowptr[i] = run;
        g_fill[i]   = run;
        run += g_cnt[i];
    }
    if (t == 1023) g_rowptr[N] = E;
}

// Fused: CSR scatter + 10-hop edge-dropout masks + edge weight, one packed 8B store.
__global__ void scatter_kernel(const int* __restrict__ index,
                               const float* __restrict__ value, int E, HopKeys hk,
                               float keep, float invkeep, float onemA) {
    int e = blockIdx.x * blockDim.x + threadIdx.x;
    if (e >= E) return;
    int r = index[e];
    unsigned c = (unsigned)index[E + e];
    unsigned mask = 0;
#pragma unroll
    for (int h = 0; h < NUM_HOPS; h++) {
        unsigned bits = tf_bits(hk.a[h], hk.b[h], (unsigned)e);
        if (tf_uniform(bits) < keep) mask |= (1u << h);
    }
    float wk = onemA * (value[e] * invkeep);   // (1-alpha) * value/keep
    unsigned long long pk =
        ((unsigned long long)__float_as_uint(wk) << 32) |
        (unsigned long long)(c | (mask << 22));
    int pos = atomicAdd(&g_fill[r], 1);
    g_cw[pos] = pk;
}

// ---------------- fp32 SIMT GEMM with fused dropout ----------------
// MODE 0: A = dropout_ka(X) on the fly; epilogue: relu then dropout_kh; -> g_H
// MODE 1: A = g_H (already dropped); plain epilogue; -> g_Z0
#define BM 64
#define BN 64
#define BK 32
template<int MODE>
__global__ __launch_bounds__(256) void gemm_kernel(const float* __restrict__ Ain,
                                                   const float* __restrict__ W,
                                                   const float* __restrict__ bias,
                                                   int Nrows, int K,
                                                   unsigned ka0, unsigned ka1,
                                                   unsigned kh0, unsigned kh1,
                                                   float keep, float invkeep) {
    const float* __restrict__ A = (MODE == 0) ? Ain : g_H;
    float* __restrict__ O       = (MODE == 0) ? g_H : g_Z0;
    __shared__ float As[BM][BK + 1];
    __shared__ float Ws[BK][BN];
    int tid = threadIdx.x;
    int tx = tid & 15, ty = tid >> 4;
    int rowBase = blockIdx.x * BM;
    float acc[4][4] = {};
    for (int k0 = 0; k0 < K; k0 += BK) {
#pragma unroll
        for (int l = 0; l < 2; l++) {
            int idx = tid + l * 256;           // A tile 64x32 = 512 float4 slots
            int r = idx >> 3, c4 = idx & 7;
            int gr = rowBase + r;
            float4 v = make_float4(0.f, 0.f, 0.f, 0.f);
            if (gr < Nrows) {
                v = *(const float4*)&A[(size_t)gr * K + k0 + c4 * 4];
                if (MODE == 0) {
                    unsigned eb = (unsigned)gr * (unsigned)K + (unsigned)(k0 + c4 * 4);
                    unsigned b0 = tf_bits(ka0, ka1, eb + 0);
                    unsigned b1 = tf_bits(ka0, ka1, eb + 1);
                    unsigned b2 = tf_bits(ka0, ka1, eb + 2);
                    unsigned b3 = tf_bits(ka0, ka1, eb + 3);
                    v.x = (tf_uniform(b0) < keep) ? v.x * invkeep : 0.f;
                    v.y = (tf_uniform(b1) < keep) ? v.y * invkeep : 0.f;
                    v.z = (tf_uniform(b2) < keep) ? v.z * invkeep : 0.f;
                    v.w = (tf_uniform(b3) < keep) ? v.w * invkeep : 0.f;
                }
            }
            As[r][c4 * 4 + 0] = v.x; As[r][c4 * 4 + 1] = v.y;
            As[r][c4 * 4 + 2] = v.z; As[r][c4 * 4 + 3] = v.w;
        }
#pragma unroll
        for (int l = 0; l < 2; l++) {
            int idx = tid + l * 256;           // W tile 32x64
            int r = idx >> 4, c4 = idx & 15;
            float4 v = *(const float4*)&W[(size_t)(k0 + r) * BN + c4 * 4];
            *(float4*)&Ws[r][c4 * 4] = v;
        }
        __syncthreads();
#pragma unroll
        for (int k = 0; k < BK; k++) {
            float a0 = As[ty * 4 + 0][k], a1 = As[ty * 4 + 1][k];
            float a2 = As[ty * 4 + 2][k], a3 = As[ty * 4 + 3][k];
            float4 w = *(float4*)&Ws[k][tx * 4];
            acc[0][0] += a0 * w.x; acc[0][1] += a0 * w.y; acc[0][2] += a0 * w.z; acc[0][3] += a0 * w.w;
            acc[1][0] += a1 * w.x; acc[1][1] += a1 * w.y; acc[1][2] += a1 * w.z; acc[1][3] += a1 * w.w;
            acc[2][0] += a2 * w.x; acc[2][1] += a2 * w.y; acc[2][2] += a2 * w.z; acc[2][3] += a2 * w.w;
            acc[3][0] += a3 * w.x; acc[3][1] += a3 * w.y; acc[3][2] += a3 * w.z; acc[3][3] += a3 * w.w;
        }
        __syncthreads();
    }
    float4 bv = *(const float4*)&bias[tx * 4];
#pragma unroll
    for (int i = 0; i < 4; i++) {
        int gr = rowBase + ty * 4 + i;
        if (gr < Nrows) {
            float4 o;
            o.x = acc[i][0] + bv.x; o.y = acc[i][1] + bv.y;
            o.z = acc[i][2] + bv.z; o.w = acc[i][3] + bv.w;
            if (MODE == 0) {
                o.x = fmaxf(o.x, 0.f); o.y = fmaxf(o.y, 0.f);
                o.z = fmaxf(o.z, 0.f); o.w = fmaxf(o.w, 0.f);
                unsigned hb = (unsigned)gr * 64u + (unsigned)(tx * 4);
                unsigned b0 = tf_bits(kh0, kh1, hb + 0);
                unsigned b1 = tf_bits(kh0, kh1, hb + 1);
                unsigned b2 = tf_bits(kh0, kh1, hb + 2);
                unsigned b3 = tf_bits(kh0, kh1, hb + 3);
                o.x = (tf_uniform(b0) < keep) ? o.x * invkeep : 0.f;
                o.y = (tf_uniform(b1) < keep) ? o.y * invkeep : 0.f;
                o.z = (tf_uniform(b2) < keep) ? o.z * invkeep : 0.f;
                o.w = (tf_uniform(b3) < keep) ? o.w * invkeep : 0.f;
            }
            *(float4*)&O[(size_t)gr * BN + tx * 4] = o;
        }
    }
}

// ---------------- propagation hop: one warp per destination row (pull, no atomics) ----------------
__global__ __launch_bounds__(256) void hop_kernel(int hop, int lastHop,
                                                  float* __restrict__ dout,
                                                  int Nrows, float alpha) {
    const float* __restrict__ Zin =
        (hop == 0) ? g_Z0 : ((hop & 1) ? g_Za : g_Zb);
    float* __restrict__ Zout =
        (hop == lastHop) ? dout : ((hop & 1) ? g_Zb : g_Za);

    int warp = (int)((blockIdx.x * (unsigned)blockDim.x + threadIdx.x) >> 5);
    int lane = threadIdx.x & 31;
    if (warp >= Nrows) return;
    int s = g_rowptr[warp];
    int e = g_rowptr[warp + 1];
    unsigned sh = 22u + (unsigned)hop;
    float ax = 0.f, ay = 0.f;
#pragma unroll 4
    for (int j = s; j < e; j++) {
        unsigned long long pk = __ldg(&g_cw[j]);
        unsigned cw = (unsigned)pk;
        if ((cw >> sh) & 1u) {
            unsigned c = cw & 0x3FFFFFu;
            float ww = __uint_as_float((unsigned)(pk >> 32));
            float2 z = *(const float2*)&Zin[(size_t)c * 64 + lane * 2];
            ax = fmaf(ww, z.x, ax);
            ay = fmaf(ww, z.y, ay);
        }
    }
    float2 z0 = *(const float2*)&g_Z0[(size_t)warp * 64 + lane * 2];
    float2 o;
    o.x = ax + alpha * z0.x;
    o.y = ay + alpha * z0.y;
    *(float2*)&Zout[(size_t)warp * 64 + lane * 2] = o;
}

// ---------------- host ----------------
extern "C" void kernel_launch(void* const* d_in, const int* in_sizes, int n_in,
                              void* d_out, int out_size) {
    const int*   index = (const int*)d_in[0];
    const float* value = (const float*)d_in[1];
    // Optional scalar "n" may appear as a size-1 input at slot 2.
    int base = (n_in >= 8 && in_sizes[2] == 1) ? 3 : 2;
    const float* X  = (const float*)d_in[base + 0];
    const float* W1 = (const float*)d_in[base + 1];
    const float* b1 = (const float*)d_in[base + 2];
    const float* W2 = (const float*)d_in[base + 3];
    const float* b2 = (const float*)d_in[base + 4];

    int E   = in_sizes[1];
    int HID = in_sizes[base + 2];
    int OUT = in_sizes[base + 4];
    int IN  = in_sizes[base + 1] / HID;
    int N   = in_sizes[base + 0] / IN;
    (void)out_size; (void)OUT;

    // ---- derive JAX keys on host (key(42), fold-like split, fold_in) ----
    unsigned rk0 = 0u, rk1 = 42u;
    unsigned kx0, kx1, kh0, kh1, ke0, ke1;
    tf_block(rk0, rk1, 0u, 0u, kx0, kx1);   // split[0]
    tf_block(rk0, rk1, 0u, 1u, kh0, kh1);   // split[1]
    tf_block(rk0, rk1, 0u, 2u, ke0, ke1);   // split[2]
    HopKeys hk;
    for (unsigned h = 0; h < NUM_HOPS; h++)
        tf_block(ke0, ke1, 0u, h, hk.a[h], hk.b[h]);   // fold_in(ke, h)

    const float keep    = 1.0f - P_DROP;          // 0.9f
    const float invkeep = 1.0f / keep;
    const float onemA   = 1.0f - ALPHA_F;

    const int T = 256;

    // ---- CSR build fused with edge-dropout masks + weights ----
    zero_cnt_kernel<<<(N + T - 1) / T, T>>>(N);
    hist_kernel<<<(E + T - 1) / T, T>>>(index, E);
    scan_kernel<<<1, 1024>>>(N, E);
    scatter_kernel<<<(E + T - 1) / T, T>>>(index, value, E, hk, keep, invkeep, onemA);

    // ---- MLP: gemm1 (fused dropout-in + relu + dropout-out) -> gemm2 ----
    gemm_kernel<0><<<(N + BM - 1) / BM, 256>>>(X, W1, b1, N, IN,
                                               kx0, kx1, kh0, kh1, keep, invkeep);
    gemm_kernel<1><<<(N + BM - 1) / BM, 256>>>(X, W2, b2, N, HID,
                                               0u, 0u, 0u, 0u, keep, invkeep);

    // ---- 10 propagation hops ----
    int hopBlocks = (N * 32 + T - 1) / T;
    for (int h = 0; h < NUM_HOPS; h++)
        hop_kernel<<<hopBlocks, T>>>(h, NUM_HOPS - 1, (float*)d_out, N, ALPHA_F);
}

// round 6
// speedup vs baseline: 1.2931x; 1.1323x over previous
#include <cuda_runtime.h>
#include <cstdint>

#define P_DROP   0.1f
#define ALPHA_F  0.1f
#define NUM_HOPS 10

// Fixed problem capacities (N=100000, E=3200000, IN=512, HID=64, OUT=64)
#define MAXN   100352
#define MAXE   3200000
#define MAXNH  6400000    // N*HID / N*OUT

// exact integer form of  (float)((bits>>9) * 2^-23) < 0.9f :  m < 7549747  <=>  bits < 7549747*512
#define KEEP_BITS_THRESH 3865470464u

// ---------------- static device scratch (no allocations allowed) ----------------
__device__ float              g_H[MAXNH];
__device__ float              g_Z0[MAXNH];
__device__ float              g_Za[MAXNH];
__device__ float              g_Zb[MAXNH];
__device__ int                g_cnt[MAXN];
__device__ int                g_rowptr[MAXN + 1];
__device__ int                g_fill[MAXN];
// packed per-CSR-position edge record: lo32 = col | (10-bit hop keep-mask << 22), hi32 = f32 weight
__device__ unsigned long long g_cw[MAXE];

// ---------------- packed f32x2 helpers (Blackwell FFMA2 path, PTX-only) ----------------
__device__ __forceinline__ void ffma2(unsigned long long& d, unsigned long long a,
                                      unsigned long long b) {
    asm("fma.rn.f32x2 %0, %1, %2, %3;" : "=l"(d) : "l"(a), "l"(b), "l"(d));
}
__device__ __forceinline__ unsigned long long packf2(float lo, float hi) {
    unsigned long long r;
    asm("mov.b64 %0, {%1, %2};" : "=l"(r) : "f"(lo), "f"(hi));
    return r;
}
__device__ __forceinline__ void unpackf2(float& lo, float& hi, unsigned long long v) {
    asm("mov.b64 {%0, %1}, %2;" : "=f"(lo), "=f"(hi) : "l"(v));
}

// ---------------- threefry-2x32 (JAX-exact, 20 rounds) ----------------
__host__ __device__ __forceinline__ void tf_block(unsigned k0, unsigned k1,
                                                  unsigned x0, unsigned x1,
                                                  unsigned& o0, unsigned& o1) {
    unsigned k2 = k0 ^ k1 ^ 0x1BD11BDAu;
    x0 += k0; x1 += k1;
#define TF_R(r) { x0 += x1; x1 = (x1 << (r)) | (x1 >> (32 - (r))); x1 ^= x0; }
    TF_R(13) TF_R(15) TF_R(26) TF_R(6)
    x0 += k1; x1 += k2 + 1u;
    TF_R(17) TF_R(29) TF_R(16) TF_R(24)
    x0 += k2; x1 += k0 + 2u;
    TF_R(13) TF_R(15) TF_R(26) TF_R(6)
    x0 += k0; x1 += k1 + 3u;
    TF_R(17) TF_R(29) TF_R(16) TF_R(24)
    x0 += k1; x1 += k2 + 4u;
    TF_R(13) TF_R(15) TF_R(26) TF_R(6)
    x0 += k2; x1 += k0 + 5u;
#undef TF_R
    o0 = x0; o1 = x1;
}

// partitionable-mode random bits: element i -> block(key, hi=0, lo=i), b1^b2
__device__ __forceinline__ unsigned tf_bits(unsigned k0, unsigned k1, unsigned lo) {
    unsigned a, b;
    tf_block(k0, k1, 0u, lo, a, b);
    return a ^ b;
}

// keep decision, integer-exact equivalent of uniform(bits) < 0.9f
__device__ __forceinline__ bool tf_keep(unsigned bits) {
    return bits < KEEP_BITS_THRESH;
}

struct HopKeys { unsigned a[NUM_HOPS]; unsigned b[NUM_HOPS]; };

// ---------------- CSR build ----------------
__global__ void zero_cnt_kernel(int n) {
    int i = blockIdx.x * blockDim.x + threadIdx.x;
    if (i < n) g_cnt[i] = 0;
}

__global__ void hist_kernel(const int* __restrict__ index, int E) {
    int e = blockIdx.x * blockDim.x + threadIdx.x;
    if (e < E) atomicAdd(&g_cnt[index[e]], 1);   // index[0..E) = row
}

__global__ void scan_kernel(int N, int E) {
    __shared__ int sm[1024];
    int t = threadIdx.x;
    int chunk = (N + 1023) >> 10;
    int beg = t * chunk; if (beg > N) beg = N;
    int end = beg + chunk; if (end > N) end = N;
    int s = 0;
    for (int i = beg; i < end; i++) s += g_cnt[i];
    sm[t] = s;
    __syncthreads();
    for (int off = 1; off < 1024; off <<= 1) {
        int v = (t >= off) ? sm[t - off] : 0;
        __syncthreads();
        sm[t] += v;
        __syncthreads();
    }
    int run = sm[t] - s;   // exclusive prefix
    for (int i = beg; i < end; i++) {
        g_rowptr[i] = run;
        g_fill[i]   = run;
        run += g_cnt[i];
    }
    if (t == 1023) g_rowptr[N] = E;
}

// Fused: CSR scatter + 10-hop edge-dropout masks + edge weight, one packed 8B store.
__global__ void scatter_kernel(const int* __restrict__ index,
                               const float* __restrict__ value, int E, HopKeys hk,
                               float invkeep, float onemA) {
    int e = blockIdx.x * blockDim.x + threadIdx.x;
    if (e >= E) return;
    int r = index[e];
    unsigned c = (unsigned)index[E + e];
    unsigned mask = 0;
#pragma unroll
    for (int h = 0; h < NUM_HOPS; h++) {
        unsigned bits = tf_bits(hk.a[h], hk.b[h], (unsigned)e);
        if (tf_keep(bits)) mask |= (1u << h);
    }
    float wk = onemA * (value[e] * invkeep);   // (1-alpha) * value/keep
    unsigned long long pk =
        ((unsigned long long)__float_as_uint(wk) << 32) |
        (unsigned long long)(c | (mask << 22));
    int pos = atomicAdd(&g_fill[r], 1);
    g_cw[pos] = pk;
}

// ---------------- fp32 SIMT GEMM with fused dropout, FFMA2 inner loop ----------------
// MODE 0: A = dropout_ka(X) on the fly; epilogue: relu then dropout_kh; -> g_H
// MODE 1: A = g_H (already dropped); plain epilogue; -> g_Z0
#define BM 64
#define BN 64
#define BK 32
template<int MODE>
__global__ __launch_bounds__(256) void gemm_kernel(const float* __restrict__ Ain,
                                                   const float* __restrict__ W,
                                                   const float* __restrict__ bias,
                                                   int Nrows, int K,
                                                   unsigned ka0, unsigned ka1,
                                                   unsigned kh0, unsigned kh1,
                                                   float invkeep) {
    const float* __restrict__ A = (MODE == 0) ? Ain : g_H;
    float* __restrict__ O       = (MODE == 0) ? g_H : g_Z0;
    __shared__ float As[BM][BK + 1];
    __shared__ float Ws[BK][BN];
    int tid = threadIdx.x;
    int tx = tid & 15, ty = tid >> 4;
    int rowBase = blockIdx.x * BM;
    unsigned long long acc2[4][2];
#pragma unroll
    for (int i = 0; i < 4; i++) { acc2[i][0] = 0ull; acc2[i][1] = 0ull; }

    for (int k0 = 0; k0 < K; k0 += BK) {
#pragma unroll
        for (int l = 0; l < 2; l++) {
            int idx = tid + l * 256;           // A tile 64x32 = 512 float4 slots
            int r = idx >> 3, c4 = idx & 7;
            int gr = rowBase + r;
            float4 v = make_float4(0.f, 0.f, 0.f, 0.f);
            if (gr < Nrows) {
                v = *(const float4*)&A[(size_t)gr * K + k0 + c4 * 4];
                if (MODE == 0) {
                    unsigned eb = (unsigned)gr * (unsigned)K + (unsigned)(k0 + c4 * 4);
                    v.x = tf_keep(tf_bits(ka0, ka1, eb + 0)) ? v.x * invkeep : 0.f;
                    v.y = tf_keep(tf_bits(ka0, ka1, eb + 1)) ? v.y * invkeep : 0.f;
                    v.z = tf_keep(tf_bits(ka0, ka1, eb + 2)) ? v.z * invkeep : 0.f;
                    v.w = tf_keep(tf_bits(ka0, ka1, eb + 3)) ? v.w * invkeep : 0.f;
                }
            }
            As[r][c4 * 4 + 0] = v.x; As[r][c4 * 4 + 1] = v.y;
            As[r][c4 * 4 + 2] = v.z; As[r][c4 * 4 + 3] = v.w;
        }
#pragma unroll
        for (int l = 0; l < 2; l++) {
            int idx = tid + l * 256;           // W tile 32x64
            int r = idx >> 4, c4 = idx & 15;
            float4 v = *(const float4*)&W[(size_t)(k0 + r) * BN + c4 * 4];
            *(float4*)&Ws[r][c4 * 4] = v;
        }
        __syncthreads();
#pragma unroll
        for (int k = 0; k < BK; k++) {
            float4 w = *(float4*)&Ws[k][tx * 4];
            unsigned long long w01 = packf2(w.x, w.y);
            unsigned long long w23 = packf2(w.z, w.w);
#pragma unroll
            for (int i = 0; i < 4; i++) {
                float a = As[ty * 4 + i][k];
                unsigned long long aa = packf2(a, a);
                ffma2(acc2[i][0], aa, w01);
                ffma2(acc2[i][1], aa, w23);
            }
        }
        __syncthreads();
    }
    float4 bv = *(const float4*)&bias[tx * 4];
#pragma unroll
    for (int i = 0; i < 4; i++) {
        int gr = rowBase + ty * 4 + i;
        if (gr < Nrows) {
            float4 o;
            unpackf2(o.x, o.y, acc2[i][0]);
            unpackf2(o.z, o.w, acc2[i][1]);
            o.x += bv.x; o.y += bv.y; o.z += bv.z; o.w += bv.w;
            if (MODE == 0) {
                o.x = fmaxf(o.x, 0.f); o.y = fmaxf(o.y, 0.f);
                o.z = fmaxf(o.z, 0.f); o.w = fmaxf(o.w, 0.f);
                unsigned hb = (unsigned)gr * 64u + (unsigned)(tx * 4);
                o.x = tf_keep(tf_bits(kh0, kh1, hb + 0)) ? o.x * invkeep : 0.f;
                o.y = tf_keep(tf_bits(kh0, kh1, hb + 1)) ? o.y * invkeep : 0.f;
                o.z = tf_keep(tf_bits(kh0, kh1, hb + 2)) ? o.z * invkeep : 0.f;
                o.w = tf_keep(tf_bits(kh0, kh1, hb + 3)) ? o.w * invkeep : 0.f;
            }
            *(float4*)&O[(size_t)gr * BN + tx * 4] = o;
        }
    }
}

// ---------------- propagation hop: 2 rows per warp (half-warp x float4), pull, no atomics ----------------
__global__ __launch_bounds__(256) void hop_kernel(int hop, int lastHop,
                                                  float* __restrict__ dout,
                                                  int Nrows, float alpha) {
    const float* __restrict__ Zin =
        (hop == 0) ? g_Z0 : ((hop & 1) ? g_Za : g_Zb);
    float* __restrict__ Zout =
        (hop == lastHop) ? dout : ((hop & 1) ? g_Zb : g_Za);

    int gw   = (int)((blockIdx.x * (unsigned)blockDim.x + threadIdx.x) >> 5);
    int half = (threadIdx.x >> 4) & 1;
    int l    = threadIdx.x & 15;
    int r    = gw * 2 + half;

    int s = 0, e = 0;
    if (r < Nrows) { s = g_rowptr[r]; e = g_rowptr[r + 1]; }
    unsigned sh = 22u + (unsigned)hop;
    float ax = 0.f, ay = 0.f, az = 0.f, aw = 0.f;
#pragma unroll 4
    for (int j = s; j < e; j++) {
        unsigned long long pk = __ldg(&g_cw[j]);
        unsigned cw = (unsigned)pk;
        if ((cw >> sh) & 1u) {
            unsigned c = cw & 0x3FFFFFu;
            float ww = __uint_as_float((unsigned)(pk >> 32));
            float4 z = *(const float4*)&Zin[(size_t)c * 64 + l * 4];
            ax = fmaf(ww, z.x, ax);
            ay = fmaf(ww, z.y, ay);
            az = fmaf(ww, z.z, az);
            aw = fmaf(ww, z.w, aw);
        }
    }
    if (r < Nrows) {
        float4 z0 = *(const float4*)&g_Z0[(size_t)r * 64 + l * 4];
        float4 o;
        o.x = ax + alpha * z0.x;
        o.y = ay + alpha * z0.y;
        o.z = az + alpha * z0.z;
        o.w = aw + alpha * z0.w;
        *(float4*)&Zout[(size_t)r * 64 + l * 4] = o;
    }
}

// ---------------- host ----------------
extern "C" void kernel_launch(void* const* d_in, const int* in_sizes, int n_in,
                              void* d_out, int out_size) {
    const int*   index = (const int*)d_in[0];
    const float* value = (const float*)d_in[1];
    // Optional scalar "n" may appear as a size-1 input at slot 2.
    int base = (n_in >= 8 && in_sizes[2] == 1) ? 3 : 2;
    const float* X  = (const float*)d_in[base + 0];
    const float* W1 = (const float*)d_in[base + 1];
    const float* b1 = (const float*)d_in[base + 2];
    const float* W2 = (const float*)d_in[base + 3];
    const float* b2 = (const float*)d_in[base + 4];

    int E   = in_sizes[1];
    int HID = in_sizes[base + 2];
    int OUT = in_sizes[base + 4];
    int IN  = in_sizes[base + 1] / HID;
    int N   = in_sizes[base + 0] / IN;
    (void)out_size; (void)OUT;

    // ---- derive JAX keys on host (key(42), fold-like split, fold_in) ----
    unsigned rk0 = 0u, rk1 = 42u;
    unsigned kx0, kx1, kh0, kh1, ke0, ke1;
    tf_block(rk0, rk1, 0u, 0u, kx0, kx1);   // split[0]
    tf_block(rk0, rk1, 0u, 1u, kh0, kh1);   // split[1]
    tf_block(rk0, rk1, 0u, 2u, ke0, ke1);   // split[2]
    HopKeys hk;
    for (unsigned h = 0; h < NUM_HOPS; h++)
        tf_block(ke0, ke1, 0u, h, hk.a[h], hk.b[h]);   // fold_in(ke, h)

    const float invkeep = 1.0f / (1.0f - P_DROP);
    const float onemA   = 1.0f - ALPHA_F;

    const int T = 256;

    // ---- CSR build fused with edge-dropout masks + weights ----
    zero_cnt_kernel<<<(N + T - 1) / T, T>>>(N);
    hist_kernel<<<(E + T - 1) / T, T>>>(index, E);
    scan_kernel<<<1, 1024>>>(N, E);
    scatter_kernel<<<(E + T - 1) / T, T>>>(index, value, E, hk, invkeep, onemA);

    // ---- MLP: gemm1 (fused dropout-in + relu + dropout-out) -> gemm2 ----
    gemm_kernel<0><<<(N + BM - 1) / BM, 256>>>(X, W1, b1, N, IN,
                                               kx0, kx1, kh0, kh1, invkeep);
    gemm_kernel<1><<<(N + BM - 1) / BM, 256>>>(X, W2, b2, N, HID,
                                               0u, 0u, 0u, 0u, invkeep);

    // ---- 10 propagation hops: 2 rows per warp ----
    int warpsNeeded = (N + 1) / 2;
    int hopBlocks = (warpsNeeded * 32 + T - 1) / T;
    for (int h = 0; h < NUM_HOPS; h++)
        hop_kernel<<<hopBlocks, T>>>(h, NUM_HOPS - 1, (float*)d_out, N, ALPHA_F);
}

// round 9
// speedup vs baseline: 1.4028x; 1.0848x over previous
#include <cuda_runtime.h>
#include <cuda_fp16.h>
#include <cstdint>

#define P_DROP   0.1f
#define ALPHA_F  0.1f
#define NUM_HOPS 10

// Fixed problem capacities (N=100000, E=3200000, IN=512, HID=64, OUT=64)
#define MAXN   100352
#define MAXE   3200000
#define MAXNH  6400000    // N*HID / N*OUT

// exact integer form of  (float)((bits>>9) * 2^-23) < 0.9f
#define KEEP_BITS_THRESH 3865470464u

// ---------------- static device scratch (no allocations allowed) ----------------
__device__ float              g_H[MAXNH];
__device__ float              g_Z0[MAXNH];    // fp32 Z0 (alpha anchor + final)
__device__ __half             g_Zh0[MAXNH];   // half Z0 (hop 0 gather input)
__device__ __half             g_Zha[MAXNH];   // ping
__device__ __half             g_Zhb[MAXNH];   // pong
__device__ int                g_cnt[MAXN];
__device__ int                g_rowptr[MAXN + 1];
__device__ int                g_fill[MAXN];
// packed per-CSR-position edge record: lo32 = col | (10-bit hop keep-mask << 22), hi32 = f32 weight
__device__ unsigned long long g_cw[MAXE];

// ---------------- packed f32x2 helpers (Blackwell FFMA2 path, PTX-only) ----------------
__device__ __forceinline__ void ffma2(unsigned long long& d, unsigned long long a,
                                      unsigned long long b) {
    asm("fma.rn.f32x2 %0, %1, %2, %3;" : "=l"(d) : "l"(a), "l"(b), "l"(d));
}
__device__ __forceinline__ unsigned long long packf2(float lo, float hi) {
    unsigned long long r;
    asm("mov.b64 %0, {%1, %2};" : "=l"(r) : "f"(lo), "f"(hi));
    return r;
}
__device__ __forceinline__ void unpackf2(float& lo, float& hi, unsigned long long v) {
    asm("mov.b64 {%0, %1}, %2;" : "=f"(lo), "=f"(hi) : "l"(v));
}

// ---------------- threefry-2x32 (JAX-exact, 20 rounds) ----------------
__host__ __device__ __forceinline__ void tf_block(unsigned k0, unsigned k1,
                                                  unsigned x0, unsigned x1,
                                                  unsigned& o0, unsigned& o1) {
    unsigned k2 = k0 ^ k1 ^ 0x1BD11BDAu;
    x0 += k0; x1 += k1;
#define TF_R(r) { x0 += x1; x1 = (x1 << (r)) | (x1 >> (32 - (r))); x1 ^= x0; }
    TF_R(13) TF_R(15) TF_R(26) TF_R(6)
    x0 += k1; x1 += k2 + 1u;
    TF_R(17) TF_R(29) TF_R(16) TF_R(24)
    x0 += k2; x1 += k0 + 2u;
    TF_R(13) TF_R(15) TF_R(26) TF_R(6)
    x0 += k0; x1 += k1 + 3u;
    TF_R(17) TF_R(29) TF_R(16) TF_R(24)
    x0 += k1; x1 += k2 + 4u;
    TF_R(13) TF_R(15) TF_R(26) TF_R(6)
    x0 += k2; x1 += k0 + 5u;
#undef TF_R
    o0 = x0; o1 = x1;
}

__device__ __forceinline__ unsigned tf_bits(unsigned k0, unsigned k1, unsigned lo) {
    unsigned a, b;
    tf_block(k0, k1, 0u, lo, a, b);
    return a ^ b;
}

__device__ __forceinline__ bool tf_keep(unsigned bits) {
    return bits < KEEP_BITS_THRESH;
}

struct HopKeys { unsigned a[NUM_HOPS]; unsigned b[NUM_HOPS]; };

// ---------------- CSR build ----------------
__global__ void zero_cnt_kernel(int n) {
    int i = blockIdx.x * blockDim.x + threadIdx.x;
    if (i < n) g_cnt[i] = 0;
}

__global__ void hist_kernel(const int* __restrict__ index, int E) {
    int e = blockIdx.x * blockDim.x + threadIdx.x;
    if (e < E) atomicAdd(&g_cnt[index[e]], 1);   // index[0..E) = row
}

__global__ void scan_kernel(int N, int E) {
    __shared__ int sm[1024];
    int t = threadIdx.x;
    int chunk = (N + 1023) >> 10;
    int beg = t * chunk; if (beg > N) beg = N;
    int end = beg + chunk; if (end > N) end = N;
    int s = 0;
    for (int i = beg; i < end; i++) s += g_cnt[i];
    sm[t] = s;
    __syncthreads();
    for (int off = 1; off < 1024; off <<= 1) {
        int v = (t >= off) ? sm[t - off] : 0;
        __syncthreads();
        sm[t] += v;
        __syncthreads();
    }
    int run = sm[t] - s;   // exclusive prefix
    for (int i = beg; i < end; i++) {
        g_rowptr[i] = run;
        g_fill[i]   = run;
        run += g_cnt[i];
    }
    if (t == 1023) g_rowptr[N] = E;
}

// Fused: CSR scatter + 10-hop edge-dropout masks + edge weight, one packed 8B store.
__global__ void scatter_kernel(const int* __restrict__ index,
                               const float* __restrict__ value, int E, HopKeys hk,
                               float invkeep, float onemA) {
    int e = blockIdx.x * blockDim.x + threadIdx.x;
    if (e >= E) return;
    int r = index[e];
    unsigned c = (unsigned)index[E + e];
    unsigned mask = 0;
#pragma unroll
    for (int h = 0; h < NUM_HOPS; h++) {
        unsigned bits = tf_bits(hk.a[h], hk.b[h], (unsigned)e);
        if (tf_keep(bits)) mask |= (1u << h);
    }
    float wk = onemA * (value[e] * invkeep);   // (1-alpha) * value/keep
    unsigned long long pk =
        ((unsigned long long)__float_as_uint(wk) << 32) |
        (unsigned long long)(c | (mask << 22));
    int pos = atomicAdd(&g_fill[r], 1);
    g_cw[pos] = pk;
}

// ---------------- fp32 SIMT GEMM with fused dropout, FFMA2 inner loop ----------------
// MODE 0: A = dropout_ka(X) on the fly; epilogue: relu then dropout_kh; -> g_H
// MODE 1: A = g_H; plain epilogue; -> g_Z0 (fp32) AND g_Zh0 (half)
#define BM 64
#define BN 64
#define BK 32
template<int MODE>
__global__ __launch_bounds__(256) void gemm_kernel(const float* __restrict__ Ain,
                                                   const float* __restrict__ W,
                                                   const float* __restrict__ bias,
                                                   int Nrows, int K,
                                                   unsigned ka0, unsigned ka1,
                                                   unsigned kh0, unsigned kh1,
                                                   float invkeep) {
    const float* __restrict__ A = (MODE == 0) ? Ain : g_H;
    float* __restrict__ O       = (MODE == 0) ? g_H : g_Z0;
    __shared__ float As[BM][BK + 1];
    __shared__ float Ws[BK][BN];
    int tid = threadIdx.x;
    int tx = tid & 15, ty = tid >> 4;
    int rowBase = blockIdx.x * BM;
    unsigned long long acc2[4][2];
#pragma unroll
    for (int i = 0; i < 4; i++) { acc2[i][0] = 0ull; acc2[i][1] = 0ull; }

    for (int k0 = 0; k0 < K; k0 += BK) {
#pragma unroll
        for (int l = 0; l < 2; l++) {
            int idx = tid + l * 256;           // A tile 64x32 = 512 float4 slots
            int r = idx >> 3, c4 = idx & 7;
            int gr = rowBase + r;
            float4 v = make_float4(0.f, 0.f, 0.f, 0.f);
            if (gr < Nrows) {
                v = *(const float4*)&A[(size_t)gr * K + k0 + c4 * 4];
                if (MODE == 0) {
                    unsigned eb = (unsigned)gr * (unsigned)K + (unsigned)(k0 + c4 * 4);
                    v.x = tf_keep(tf_bits(ka0, ka1, eb + 0)) ? v.x * invkeep : 0.f;
                    v.y = tf_keep(tf_bits(ka0, ka1, eb + 1)) ? v.y * invkeep : 0.f;
                    v.z = tf_keep(tf_bits(ka0, ka1, eb + 2)) ? v.z * invkeep : 0.f;
                    v.w = tf_keep(tf_bits(ka0, ka1, eb + 3)) ? v.w * invkeep : 0.f;
                }
            }
            As[r][c4 * 4 + 0] = v.x; As[r][c4 * 4 + 1] = v.y;
            As[r][c4 * 4 + 2] = v.z; As[r][c4 * 4 + 3] = v.w;
        }
#pragma unroll
        for (int l = 0; l < 2; l++) {
            int idx = tid + l * 256;           // W tile 32x64
            int r = idx >> 4, c4 = idx & 15;
            float4 v = *(const float4*)&W[(size_t)(k0 + r) * BN + c4 * 4];
            *(float4*)&Ws[r][c4 * 4] = v;
        }
        __syncthreads();
#pragma unroll
        for (int k = 0; k < BK; k++) {
            float4 w = *(float4*)&Ws[k][tx * 4];
            unsigned long long w01 = packf2(w.x, w.y);
            unsigned long long w23 = packf2(w.z, w.w);
#pragma unroll
            for (int i = 0; i < 4; i++) {
                float a = As[ty * 4 + i][k];
                unsigned long long aa = packf2(a, a);
                ffma2(acc2[i][0], aa, w01);
                ffma2(acc2[i][1], aa, w23);
            }
        }
        __syncthreads();
    }
    float4 bv = *(const float4*)&bias[tx * 4];
#pragma unroll
    for (int i = 0; i < 4; i++) {
        int gr = rowBase + ty * 4 + i;
        if (gr < Nrows) {
            float4 o;
            unpackf2(o.x, o.y, acc2[i][0]);
            unpackf2(o.z, o.w, acc2[i][1]);
            o.x += bv.x; o.y += bv.y; o.z += bv.z; o.w += bv.w;
            if (MODE == 0) {
                o.x = fmaxf(o.x, 0.f); o.y = fmaxf(o.y, 0.f);
                o.z = fmaxf(o.z, 0.f); o.w = fmaxf(o.w, 0.f);
                unsigned hb = (unsigned)gr * 64u + (unsigned)(tx * 4);
                o.x = tf_keep(tf_bits(kh0, kh1, hb + 0)) ? o.x * invkeep : 0.f;
                o.y = tf_keep(tf_bits(kh0, kh1, hb + 1)) ? o.y * invkeep : 0.f;
                o.z = tf_keep(tf_bits(kh0, kh1, hb + 2)) ? o.z * invkeep : 0.f;
                o.w = tf_keep(tf_bits(kh0, kh1, hb + 3)) ? o.w * invkeep : 0.f;
            }
            *(float4*)&O[(size_t)gr * BN + tx * 4] = o;
            if (MODE == 1) {
                // half copy for the hop-0 gather
                __half2 h01 = __floats2half2_rn(o.x, o.y);
                __half2 h23 = __floats2half2_rn(o.z, o.w);
                uint2 hp;
                hp.x = *(unsigned*)&h01;
                hp.y = *(unsigned*)&h23;
                *(uint2*)&g_Zh0[(size_t)gr * BN + tx * 4] = hp;
            }
        }
    }
}

// ---------------- propagation hop: half Z gather, fp32 accumulate, exact 16^-h scaling ----------------
// Zs_h = Z_h * 16^-h.   Zs_{h+1} = (sum w*Zs_h) * (1/16) + (alpha*16^-(h+1)) * Z0
// Last hop: out_fp32   = (sum w*Zs_9) * 16^9 + alpha * Z0
__global__ __launch_bounds__(256) void hop_kernel(int hop, float* __restrict__ dout,
                                                  int Nrows, float mulA, float mulB) {
    const __half* __restrict__ Zin =
        (hop == 0) ? g_Zh0 : ((hop & 1) ? g_Zha : g_Zhb);
    __half* __restrict__ Zout = (hop & 1) ? g_Zhb : g_Zha;
    bool isLast = (hop == NUM_HOPS - 1);

    int gw   = (int)((blockIdx.x * (unsigned)blockDim.x + threadIdx.x) >> 5);
    int half_id = (threadIdx.x >> 4) & 1;
    int l    = threadIdx.x & 15;
    int r    = gw * 2 + half_id;

    int s = 0, e = 0;
    if (r < Nrows) { s = g_rowptr[r]; e = g_rowptr[r + 1]; }
    unsigned sh = 22u + (unsigned)hop;
    float ax = 0.f, ay = 0.f, az = 0.f, aw = 0.f;
    int j = s;
    for (; j + 2 <= e; j += 2) {
        unsigned long long pk0 = __ldg(&g_cw[j]);
        unsigned long long pk1 = __ldg(&g_cw[j + 1]);
        unsigned cw0 = (unsigned)pk0;
        unsigned cw1 = (unsigned)pk1;
        if ((cw0 >> sh) & 1u) {
            float ww = __uint_as_float((unsigned)(pk0 >> 32));
            uint2 raw = *(const uint2*)&Zin[(size_t)(cw0 & 0x3FFFFFu) * 64 + l * 4];
            float2 z01 = __half22float2(*(const __half2*)&raw.x);
            float2 z23 = __half22float2(*(const __half2*)&raw.y);
            ax = fmaf(ww, z01.x, ax);
            ay = fmaf(ww, z01.y, ay);
            az = fmaf(ww, z23.x, az);
            aw = fmaf(ww, z23.y, aw);
        }
        if ((cw1 >> sh) & 1u) {
            float ww = __uint_as_float((unsigned)(pk1 >> 32));
            uint2 raw = *(const uint2*)&Zin[(size_t)(cw1 & 0x3FFFFFu) * 64 + l * 4];
            float2 z01 = __half22float2(*(const __half2*)&raw.x);
            float2 z23 = __half22float2(*(const __half2*)&raw.y);
            ax = fmaf(ww, z01.x, ax);
            ay = fmaf(ww, z01.y, ay);
            az = fmaf(ww, z23.x, az);
            aw = fmaf(ww, z23.y, aw);
        }
    }
    for (; j < e; j++) {
        unsigned long long pk = __ldg(&g_cw[j]);
        unsigned cw = (unsigned)pk;
        if ((cw >> sh) & 1u) {
            float ww = __uint_as_float((unsigned)(pk >> 32));
            uint2 raw = *(const uint2*)&Zin[(size_t)(cw & 0x3FFFFFu) * 64 + l * 4];
            float2 z01 = __half22float2(*(const __half2*)&raw.x);
            float2 z23 = __half22float2(*(const __half2*)&raw.y);
            ax = fmaf(ww, z01.x, ax);
            ay = fmaf(ww, z01.y, ay);
            az = fmaf(ww, z23.x, az);
            aw = fmaf(ww, z23.y, aw);
        }
    }
    if (r < Nrows) {
        float4 z0 = *(const float4*)&g_Z0[(size_t)r * 64 + l * 4];
        float ox = ax * mulA + mulB * z0.x;
        float oy = ay * mulA + mulB * z0.y;
        float oz = az * mulA + mulB * z0.z;
        float ow = aw * mulA + mulB * z0.w;
        if (isLast) {
            float4 o = make_float4(ox, oy, oz, ow);
            *(float4*)&dout[(size_t)r * 64 + l * 4] = o;
        } else {
            __half2 h01 = __floats2half2_rn(ox, oy);
            __half2 h23 = __floats2half2_rn(oz, ow);
            uint2 hp;
            hp.x = *(unsigned*)&h01;
            hp.y = *(unsigned*)&h23;
            *(uint2*)&Zout[(size_t)r * 64 + l * 4] = hp;
        }
    }
}

// ---------------- host ----------------
extern "C" void kernel_launch(void* const* d_in, const int* in_sizes, int n_in,
                              void* d_out, int out_size) {
    const int*   index = (const int*)d_in[0];
    const float* value = (const float*)d_in[1];
    // Optional scalar "n" may appear as a size-1 input at slot 2.
    int base = (n_in >= 8 && in_sizes[2] == 1) ? 3 : 2;
    const float* X  = (const float*)d_in[base + 0];
    const float* W1 = (const float*)d_in[base + 1];
    const float* b1 = (const float*)d_in[base + 2];
    const float* W2 = (const float*)d_in[base + 3];
    const float* b2 = (const float*)d_in[base + 4];

    int E   = in_sizes[1];
    int HID = in_sizes[base + 2];
    int OUT = in_sizes[base + 4];
    int IN  = in_sizes[base + 1] / HID;
    int N   = in_sizes[base + 0] / IN;
    (void)out_size; (void)OUT;

    // ---- derive JAX keys on host (key(42), fold-like split, fold_in) ----
    unsigned rk0 = 0u, rk1 = 42u;
    unsigned kx0, kx1, kh0, kh1, ke0, ke1;
    tf_block(rk0, rk1, 0u, 0u, kx0, kx1);   // split[0]
    tf_block(rk0, rk1, 0u, 1u, kh0, kh1);   // split[1]
    tf_block(rk0, rk1, 0u, 2u, ke0, ke1);   // split[2]
    HopKeys hk;
    for (unsigned h = 0; h < NUM_HOPS; h++)
        tf_block(ke0, ke1, 0u, h, hk.a[h], hk.b[h]);   // fold_in(ke, h)

    const float invkeep = 1.0f / (1.0f - P_DROP);
    const float onemA   = 1.0f - ALPHA_F;

    const int T = 256;

    // ---- CSR build fused with edge-dropout masks + weights ----
    zero_cnt_kernel<<<(N + T - 1) / T, T>>>(N);
    hist_kernel<<<(E + T - 1) / T, T>>>(index, E);
    scan_kernel<<<1, 1024>>>(N, E);
    scatter_kernel<<<(E + T - 1) / T, T>>>(index, value, E, hk, invkeep, onemA);

    // ---- MLP: gemm1 (fused dropout-in + relu + dropout-out) -> gemm2 ----
    gemm_kernel<0><<<(N + BM - 1) / BM, 256>>>(X, W1, b1, N, IN,
                                               kx0, kx1, kh0, kh1, invkeep);
    gemm_kernel<1><<<(N + BM - 1) / BM, 256>>>(X, W2, b2, N, HID,
                                               0u, 0u, 0u, 0u, invkeep);

    // ---- 10 propagation hops, half Z storage with exact 2^-4h scaling ----
    int warpsNeeded = (N + 1) / 2;
    int hopBlocks = (warpsNeeded * 32 + T - 1) / T;
    for (int h = 0; h < NUM_HOPS; h++) {
        float mulA, mulB;
        if (h == NUM_HOPS - 1) {
            mulA = ldexpf(1.0f, 4 * (NUM_HOPS - 1));   // 16^9, exact
            mulB = ALPHA_F;
        } else {
            mulA = 0.0625f;                            // 1/16, exact
            mulB = ALPHA_F * ldexpf(1.0f, -4 * (h + 1));
        }
        hop_kernel<<<hopBlocks, T>>>(h, (float*)d_out, N, mulA, mulB);
    }
}

// round 10
// speedup vs baseline: 1.5007x; 1.0698x over previous
#include <cuda_runtime.h>
#include <cuda_fp16.h>
#include <cstdint>

#define P_DROP   0.1f
#define ALPHA_F  0.1f
#define NUM_HOPS 10

// Fixed problem capacities (N=100000, E=3200000, IN=512, HID=64, OUT=64)
#define MAXN   100352
#define MAXE   3200000
#define MAXNH  6400000    // N*HID / N*OUT

// exact integer form of  (float)((bits>>9) * 2^-23) < 0.9f
#define KEEP_BITS_THRESH 3865470464u

// ---------------- static device scratch (no allocations allowed) ----------------
__device__ float              g_H[MAXNH];
__device__ float              g_Z0[MAXNH];    // fp32 Z0 (alpha anchor + final)
__device__ __half             g_Zh0[MAXNH];   // half Z0 (hop 0 gather input)
__device__ __half             g_Zha[MAXNH];   // ping
__device__ __half             g_Zhb[MAXNH];   // pong
__device__ int                g_cnt[MAXN];
__device__ int                g_rowptr[MAXN + 1];
__device__ int                g_fill[MAXN];
// packed per-CSR-position edge record: lo32 = col | (10-bit hop keep-mask << 22), hi32 = f32 weight
__device__ unsigned long long g_cw[MAXE];

// ---------------- packed f32x2 helpers (Blackwell FFMA2 path, PTX-only) ----------------
__device__ __forceinline__ void ffma2(unsigned long long& d, unsigned long long a,
                                      unsigned long long b) {
    asm("fma.rn.f32x2 %0, %1, %2, %3;" : "=l"(d) : "l"(a), "l"(b), "l"(d));
}
__device__ __forceinline__ unsigned long long packf2(float lo, float hi) {
    unsigned long long r;
    asm("mov.b64 %0, {%1, %2};" : "=l"(r) : "f"(lo), "f"(hi));
    return r;
}
__device__ __forceinline__ void unpackf2(float& lo, float& hi, unsigned long long v) {
    asm("mov.b64 {%0, %1}, %2;" : "=f"(lo), "=f"(hi) : "l"(v));
}

// ---------------- threefry-2x32 (JAX-exact, 20 rounds) ----------------
__host__ __device__ __forceinline__ void tf_block(unsigned k0, unsigned k1,
                                                  unsigned x0, unsigned x1,
                                                  unsigned& o0, unsigned& o1) {
    unsigned k2 = k0 ^ k1 ^ 0x1BD11BDAu;
    x0 += k0; x1 += k1;
#define TF_R(r) { x0 += x1; x1 = (x1 << (r)) | (x1 >> (32 - (r))); x1 ^= x0; }
    TF_R(13) TF_R(15) TF_R(26) TF_R(6)
    x0 += k1; x1 += k2 + 1u;
    TF_R(17) TF_R(29) TF_R(16) TF_R(24)
    x0 += k2; x1 += k0 + 2u;
    TF_R(13) TF_R(15) TF_R(26) TF_R(6)
    x0 += k0; x1 += k1 + 3u;
    TF_R(17) TF_R(29) TF_R(16) TF_R(24)
    x0 += k1; x1 += k2 + 4u;
    TF_R(13) TF_R(15) TF_R(26) TF_R(6)
    x0 += k2; x1 += k0 + 5u;
#undef TF_R
    o0 = x0; o1 = x1;
}

__device__ __forceinline__ unsigned tf_bits(unsigned k0, unsigned k1, unsigned lo) {
    unsigned a, b;
    tf_block(k0, k1, 0u, lo, a, b);
    return a ^ b;
}

__device__ __forceinline__ bool tf_keep(unsigned bits) {
    return bits < KEEP_BITS_THRESH;
}

struct HopKeys { unsigned a[NUM_HOPS]; unsigned b[NUM_HOPS]; };

// ---------------- CSR build ----------------
__global__ void zero_cnt_kernel(int n) {
    int i = blockIdx.x * blockDim.x + threadIdx.x;
    if (i < n) g_cnt[i] = 0;
}

__global__ void hist_kernel(const int* __restrict__ index, int E) {
    int e = blockIdx.x * blockDim.x + threadIdx.x;
    if (e < E) atomicAdd(&g_cnt[index[e]], 1);   // index[0..E) = row
}

__global__ void scan_kernel(int N, int E) {
    __shared__ int sm[1024];
    int t = threadIdx.x;
    int chunk = (N + 1023) >> 10;
    int beg = t * chunk; if (beg > N) beg = N;
    int end = beg + chunk; if (end > N) end = N;
    int s = 0;
    for (int i = beg; i < end; i++) s += g_cnt[i];
    sm[t] = s;
    __syncthreads();
    for (int off = 1; off < 1024; off <<= 1) {
        int v = (t >= off) ? sm[t - off] : 0;
        __syncthreads();
        sm[t] += v;
        __syncthreads();
    }
    int run = sm[t] - s;   // exclusive prefix
    for (int i = beg; i < end; i++) {
        g_rowptr[i] = run;
        g_fill[i]   = run;
        run += g_cnt[i];
    }
    if (t == 1023) g_rowptr[N] = E;
}

// Fused: CSR scatter + 10-hop edge-dropout masks + edge weight, one packed 8B store.
__global__ void scatter_kernel(const int* __restrict__ index,
                               const float* __restrict__ value, int E, HopKeys hk,
                               float invkeep, float onemA) {
    int e = blockIdx.x * blockDim.x + threadIdx.x;
    if (e >= E) return;
    int r = index[e];
    unsigned c = (unsigned)index[E + e];
    unsigned mask = 0;
#pragma unroll
    for (int h = 0; h < NUM_HOPS; h++) {
        unsigned bits = tf_bits(hk.a[h], hk.b[h], (unsigned)e);
        if (tf_keep(bits)) mask |= (1u << h);
    }
    float wk = onemA * (value[e] * invkeep);   // (1-alpha) * value/keep
    unsigned long long pk =
        ((unsigned long long)__float_as_uint(wk) << 32) |
        (unsigned long long)(c | (mask << 22));
    int pos = atomicAdd(&g_fill[r], 1);
    g_cw[pos] = pk;
}

// ---------------- fp32 SIMT GEMM with fused dropout, FFMA2 inner loop ----------------
// MODE 0: A = dropout_ka(X) on the fly; epilogue: relu then dropout_kh; -> g_H
// MODE 1: A = g_H; plain epilogue; -> g_Z0 (fp32) AND g_Zh0 (half)
#define BM 64
#define BN 64
#define BK 32
template<int MODE>
__global__ __launch_bounds__(256) void gemm_kernel(const float* __restrict__ Ain,
                                                   const float* __restrict__ W,
                                                   const float* __restrict__ bias,
                                                   int Nrows, int K,
                                                   unsigned ka0, unsigned ka1,
                                                   unsigned kh0, unsigned kh1,
                                                   float invkeep) {
    const float* __restrict__ A = (MODE == 0) ? Ain : g_H;
    float* __restrict__ O       = (MODE == 0) ? g_H : g_Z0;
    __shared__ float As[BM][BK + 1];
    __shared__ float Ws[BK][BN];
    int tid = threadIdx.x;
    int tx = tid & 15, ty = tid >> 4;
    int rowBase = blockIdx.x * BM;
    unsigned long long acc2[4][2];
#pragma unroll
    for (int i = 0; i < 4; i++) { acc2[i][0] = 0ull; acc2[i][1] = 0ull; }

    for (int k0 = 0; k0 < K; k0 += BK) {
#pragma unroll
        for (int l = 0; l < 2; l++) {
            int idx = tid + l * 256;           // A tile 64x32 = 512 float4 slots
            int r = idx >> 3, c4 = idx & 7;
            int gr = rowBase + r;
            float4 v = make_float4(0.f, 0.f, 0.f, 0.f);
            if (gr < Nrows) {
                v = *(const float4*)&A[(size_t)gr * K + k0 + c4 * 4];
                if (MODE == 0) {
                    unsigned eb = (unsigned)gr * (unsigned)K + (unsigned)(k0 + c4 * 4);
                    v.x = tf_keep(tf_bits(ka0, ka1, eb + 0)) ? v.x * invkeep : 0.f;
                    v.y = tf_keep(tf_bits(ka0, ka1, eb + 1)) ? v.y * invkeep : 0.f;
                    v.z = tf_keep(tf_bits(ka0, ka1, eb + 2)) ? v.z * invkeep : 0.f;
                    v.w = tf_keep(tf_bits(ka0, ka1, eb + 3)) ? v.w * invkeep : 0.f;
                }
            }
            As[r][c4 * 4 + 0] = v.x; As[r][c4 * 4 + 1] = v.y;
            As[r][c4 * 4 + 2] = v.z; As[r][c4 * 4 + 3] = v.w;
        }
#pragma unroll
        for (int l = 0; l < 2; l++) {
            int idx = tid + l * 256;           // W tile 32x64
            int r = idx >> 4, c4 = idx & 15;
            float4 v = *(const float4*)&W[(size_t)(k0 + r) * BN + c4 * 4];
            *(float4*)&Ws[r][c4 * 4] = v;
        }
        __syncthreads();
#pragma unroll
        for (int k = 0; k < BK; k++) {
            float4 w = *(float4*)&Ws[k][tx * 4];
            unsigned long long w01 = packf2(w.x, w.y);
            unsigned long long w23 = packf2(w.z, w.w);
#pragma unroll
            for (int i = 0; i < 4; i++) {
                float a = As[ty * 4 + i][k];
                unsigned long long aa = packf2(a, a);
                ffma2(acc2[i][0], aa, w01);
                ffma2(acc2[i][1], aa, w23);
            }
        }
        __syncthreads();
    }
    float4 bv = *(const float4*)&bias[tx * 4];
#pragma unroll
    for (int i = 0; i < 4; i++) {
        int gr = rowBase + ty * 4 + i;
        if (gr < Nrows) {
            float4 o;
            unpackf2(o.x, o.y, acc2[i][0]);
            unpackf2(o.z, o.w, acc2[i][1]);
            o.x += bv.x; o.y += bv.y; o.z += bv.z; o.w += bv.w;
            if (MODE == 0) {
                o.x = fmaxf(o.x, 0.f); o.y = fmaxf(o.y, 0.f);
                o.z = fmaxf(o.z, 0.f); o.w = fmaxf(o.w, 0.f);
                unsigned hb = (unsigned)gr * 64u + (unsigned)(tx * 4);
                o.x = tf_keep(tf_bits(kh0, kh1, hb + 0)) ? o.x * invkeep : 0.f;
                o.y = tf_keep(tf_bits(kh0, kh1, hb + 1)) ? o.y * invkeep : 0.f;
                o.z = tf_keep(tf_bits(kh0, kh1, hb + 2)) ? o.z * invkeep : 0.f;
                o.w = tf_keep(tf_bits(kh0, kh1, hb + 3)) ? o.w * invkeep : 0.f;
            }
            *(float4*)&O[(size_t)gr * BN + tx * 4] = o;
            if (MODE == 1) {
                // half copy for the hop-0 gather
                __half2 h01 = __floats2half2_rn(o.x, o.y);
                __half2 h23 = __floats2half2_rn(o.z, o.w);
                uint2 hp;
                hp.x = *(unsigned*)&h01;
                hp.y = *(unsigned*)&h23;
                *(uint2*)&g_Zh0[(size_t)gr * BN + tx * 4] = hp;
            }
        }
    }
}

// ---------------- propagation hop: half Z gather, fp32 accumulate, exact 16^-h scaling ----------------
// Branch-free body: dropped edges contribute 0 via ww=0 (exact).  #pragma unroll 4
// lets ptxas front-batch 4 cw loads then 4 Z loads (MLP ~8 vs ~2 before).
__global__ __launch_bounds__(256) void hop_kernel(int hop, float* __restrict__ dout,
                                                  int Nrows, float mulA, float mulB) {
    const __half* __restrict__ Zin =
        (hop == 0) ? g_Zh0 : ((hop & 1) ? g_Zha : g_Zhb);
    __half* __restrict__ Zout = (hop & 1) ? g_Zhb : g_Zha;
    bool isLast = (hop == NUM_HOPS - 1);

    int gw   = (int)((blockIdx.x * (unsigned)blockDim.x + threadIdx.x) >> 5);
    int half_id = (threadIdx.x >> 4) & 1;
    int l    = threadIdx.x & 15;
    int r    = gw * 2 + half_id;

    int s = 0, e = 0;
    if (r < Nrows) { s = g_rowptr[r]; e = g_rowptr[r + 1]; }
    unsigned sh = 22u + (unsigned)hop;
    float ax = 0.f, ay = 0.f, az = 0.f, aw = 0.f;
#pragma unroll 4
    for (int j = s; j < e; j++) {
        unsigned long long pk = __ldg(&g_cw[j]);
        unsigned cw = (unsigned)pk;
        float ww = ((cw >> sh) & 1u) ? __uint_as_float((unsigned)(pk >> 32)) : 0.0f;
        uint2 raw = *(const uint2*)&Zin[(size_t)(cw & 0x3FFFFFu) * 64 + l * 4];
        float2 z01 = __half22float2(*(const __half2*)&raw.x);
        float2 z23 = __half22float2(*(const __half2*)&raw.y);
        ax = fmaf(ww, z01.x, ax);
        ay = fmaf(ww, z01.y, ay);
        az = fmaf(ww, z23.x, az);
        aw = fmaf(ww, z23.y, aw);
    }
    if (r < Nrows) {
        float4 z0 = *(const float4*)&g_Z0[(size_t)r * 64 + l * 4];
        float ox = ax * mulA + mulB * z0.x;
        float oy = ay * mulA + mulB * z0.y;
        float oz = az * mulA + mulB * z0.z;
        float ow = aw * mulA + mulB * z0.w;
        if (isLast) {
            float4 o = make_float4(ox, oy, oz, ow);
            *(float4*)&dout[(size_t)r * 64 + l * 4] = o;
        } else {
            __half2 h01 = __floats2half2_rn(ox, oy);
            __half2 h23 = __floats2half2_rn(oz, ow);
            uint2 hp;
            hp.x = *(unsigned*)&h01;
            hp.y = *(unsigned*)&h23;
            *(uint2*)&Zout[(size_t)r * 64 + l * 4] = hp;
        }
    }
}

// ---------------- host ----------------
extern "C" void kernel_launch(void* const* d_in, const int* in_sizes, int n_in,
                              void* d_out, int out_size) {
    const int*   index = (const int*)d_in[0];
    const float* value = (const float*)d_in[1];
    // Optional scalar "n" may appear as a size-1 input at slot 2.
    int base = (n_in >= 8 && in_sizes[2] == 1) ? 3 : 2;
    const float* X  = (const float*)d_in[base + 0];
    const float* W1 = (const float*)d_in[base + 1];
    const float* b1 = (const float*)d_in[base + 2];
    const float* W2 = (const float*)d_in[base + 3];
    const float* b2 = (const float*)d_in[base + 4];

    int E   = in_sizes[1];
    int HID = in_sizes[base + 2];
    int OUT = in_sizes[base + 4];
    int IN  = in_sizes[base + 1] / HID;
    int N   = in_sizes[base + 0] / IN;
    (void)out_size; (void)OUT;

    // ---- derive JAX keys on host (key(42), fold-like split, fold_in) ----
    unsigned rk0 = 0u, rk1 = 42u;
    unsigned kx0, kx1, kh0, kh1, ke0, ke1;
    tf_block(rk0, rk1, 0u, 0u, kx0, kx1);   // split[0]
    tf_block(rk0, rk1, 0u, 1u, kh0, kh1);   // split[1]
    tf_block(rk0, rk1, 0u, 2u, ke0, ke1);   // split[2]
    HopKeys hk;
    for (unsigned h = 0; h < NUM_HOPS; h++)
        tf_block(ke0, ke1, 0u, h, hk.a[h], hk.b[h]);   // fold_in(ke, h)

    const float invkeep = 1.0f / (1.0f - P_DROP);
    const float onemA   = 1.0f - ALPHA_F;

    const int T = 256;

    // ---- CSR build fused with edge-dropout masks + weights ----
    zero_cnt_kernel<<<(N + T - 1) / T, T>>>(N);
    hist_kernel<<<(E + T - 1) / T, T>>>(index, E);
    scan_kernel<<<1, 1024>>>(N, E);
    scatter_kernel<<<(E + T - 1) / T, T>>>(index, value, E, hk, invkeep, onemA);

    // ---- MLP: gemm1 (fused dropout-in + relu + dropout-out) -> gemm2 ----
    gemm_kernel<0><<<(N + BM - 1) / BM, 256>>>(X, W1, b1, N, IN,
                                               kx0, kx1, kh0, kh1, invkeep);
    gemm_kernel<1><<<(N + BM - 1) / BM, 256>>>(X, W2, b2, N, HID,
                                               0u, 0u, 0u, 0u, invkeep);

    // ---- 10 propagation hops, half Z storage with exact 2^-4h scaling ----
    int warpsNeeded = (N + 1) / 2;
    int hopBlocks = (warpsNeeded * 32 + T - 1) / T;
    for (int h = 0; h < NUM_HOPS; h++) {
        float mulA, mulB;
        if (h == NUM_HOPS - 1) {
            mulA = ldexpf(1.0f, 4 * (NUM_HOPS - 1));   // 16^9, exact
            mulB = ALPHA_F;
        } else {
            mulA = 0.0625f;                            // 1/16, exact
            mulB = ALPHA_F * ldexpf(1.0f, -4 * (h + 1));
        }
        hop_kernel<<<hopBlocks, T>>>(h, (float*)d_out, N, mulA, mulB);
    }
}